// round 1
// baseline (speedup 1.0000x reference)
#include <cuda_runtime.h>
#include <cuda_bf16.h>
#include <cstdint>

// Problem constants (fixed by the reference setup_inputs)
#define N_VARS_MAX    1000000
#define N_CONSTRS_MAX 500000

// Scratch (no cudaMalloc allowed)
__device__ float  g_probs[N_VARS_MAX];
__device__ float  g_ax[N_CONSTRS_MAX];
__device__ double g_sum;

// ---------------------------------------------------------------------------
// Kernel 1: probs = sigmoid(pred); zero ax; zero accumulator
// ---------------------------------------------------------------------------
__global__ void init_kernel(const float* __restrict__ pred, int n_vars, int n_constrs)
{
    int i = blockIdx.x * blockDim.x + threadIdx.x;
    if (i < n_vars) {
        float x = pred[i];
        g_probs[i] = 1.0f / (1.0f + __expf(-x));
    }
    if (i < n_constrs) {
        g_ax[i] = 0.0f;
    }
    if (i == 0) {
        g_sum = 0.0;
    }
}

// ---------------------------------------------------------------------------
// Kernel 2: scatter — ax[cidx] += coeff * probs[vidx]   (20M nnz)
// Vectorized x4 loads of the three streams; atomicAdd (no return -> RED).
// ---------------------------------------------------------------------------
__global__ void scatter_kernel(const int*   __restrict__ constr_idx,
                               const int*   __restrict__ var_idx,
                               const float* __restrict__ coeff,
                               int nnz)
{
    int nvec = nnz >> 2;  // number of full int4 groups
    const int4*   ci4 = reinterpret_cast<const int4*>(constr_idx);
    const int4*   vi4 = reinterpret_cast<const int4*>(var_idx);
    const float4* co4 = reinterpret_cast<const float4*>(coeff);

    int stride = gridDim.x * blockDim.x;
    for (int i = blockIdx.x * blockDim.x + threadIdx.x; i < nvec; i += stride) {
        int4   ci = ci4[i];
        int4   vi = vi4[i];
        float4 co = co4[i];

        float p0 = g_probs[vi.x];
        float p1 = g_probs[vi.y];
        float p2 = g_probs[vi.z];
        float p3 = g_probs[vi.w];

        atomicAdd(&g_ax[ci.x], co.x * p0);
        atomicAdd(&g_ax[ci.y], co.y * p1);
        atomicAdd(&g_ax[ci.z], co.z * p2);
        atomicAdd(&g_ax[ci.w], co.w * p3);
    }

    // scalar tail (nnz not divisible by 4)
    int tail_start = nvec << 2;
    for (int i = tail_start + blockIdx.x * blockDim.x + threadIdx.x; i < nnz; i += stride) {
        atomicAdd(&g_ax[constr_idx[i]], coeff[i] * g_probs[var_idx[i]]);
    }
}

// ---------------------------------------------------------------------------
// Kernel 3: per-constraint violation + block reduction -> double atomic
// ---------------------------------------------------------------------------
__global__ void reduce_kernel(const float* __restrict__ rhs,
                              const int*   __restrict__ sense,
                              int n_constrs)
{
    float local = 0.0f;
    int stride = gridDim.x * blockDim.x;
    for (int i = blockIdx.x * blockDim.x + threadIdx.x; i < n_constrs; i += stride) {
        float ax = g_ax[i];
        float r  = rhs[i];
        int   s  = sense[i];
        float d  = ax - r;
        float v;
        if (s == 1)      v = fmaxf(d, 0.0f);   // <=
        else if (s == 2) v = fmaxf(-d, 0.0f);  // >=
        else if (s == 3) v = fabsf(d);         // ==
        else             v = 0.0f;
        local += v;
    }

    // warp reduce
    #pragma unroll
    for (int off = 16; off > 0; off >>= 1)
        local += __shfl_xor_sync(0xFFFFFFFFu, local, off);

    // block reduce via shared
    __shared__ float warp_sums[32];
    int lane = threadIdx.x & 31;
    int wid  = threadIdx.x >> 5;
    if (lane == 0) warp_sums[wid] = local;
    __syncthreads();
    int nwarps = blockDim.x >> 5;
    if (wid == 0) {
        float b = (lane < nwarps) ? warp_sums[lane] : 0.0f;
        #pragma unroll
        for (int off = 16; off > 0; off >>= 1)
            b += __shfl_xor_sync(0xFFFFFFFFu, b, off);
        if (lane == 0)
            atomicAdd(&g_sum, (double)b);
    }
}

// ---------------------------------------------------------------------------
// Kernel 4: finalize — mean
// ---------------------------------------------------------------------------
__global__ void finalize_kernel(float* __restrict__ out, int n_constrs)
{
    if (threadIdx.x == 0 && blockIdx.x == 0)
        out[0] = (float)(g_sum / (double)n_constrs);
}

// ---------------------------------------------------------------------------
// Launch
// Inputs (metadata order): pred[f32 n_vars], constr_idx[i32 nnz],
// var_idx[i32 nnz], coeff[f32 nnz], constr_rhs[f32 n_constrs],
// constr_sense[i32 n_constrs], (n_vars, n_constrs scalars — derive from sizes)
// ---------------------------------------------------------------------------
extern "C" void kernel_launch(void* const* d_in, const int* in_sizes, int n_in,
                              void* d_out, int out_size)
{
    const float* pred       = (const float*)d_in[0];
    const int*   constr_idx = (const int*)  d_in[1];
    const int*   var_idx    = (const int*)  d_in[2];
    const float* coeff      = (const float*)d_in[3];
    const float* rhs        = (const float*)d_in[4];
    const int*   sense      = (const int*)  d_in[5];

    int n_vars    = in_sizes[0];
    int nnz       = in_sizes[1];
    int n_constrs = in_sizes[4];

    // 1) init
    {
        int n = (n_vars > n_constrs) ? n_vars : n_constrs;
        int threads = 256;
        int blocks  = (n + threads - 1) / threads;
        init_kernel<<<blocks, threads>>>(pred, n_vars, n_constrs);
    }

    // 2) scatter
    {
        int threads = 256;
        int work    = nnz >> 2;
        int blocks  = (work + threads - 1) / threads;
        if (blocks > 8 * 1184) blocks = 8 * 1184;  // cap; grid-stride covers rest
        scatter_kernel<<<blocks, threads>>>(constr_idx, var_idx, coeff, nnz);
    }

    // 3) reduce
    {
        int threads = 256;
        int blocks  = (n_constrs + threads * 8 - 1) / (threads * 8);
        reduce_kernel<<<blocks, threads>>>(rhs, sense, n_constrs);
    }

    // 4) finalize
    finalize_kernel<<<1, 1>>>((float*)d_out, n_constrs);
}

// round 2
// speedup vs baseline: 1.0249x; 1.0249x over previous
#include <cuda_runtime.h>
#include <cuda_bf16.h>
#include <cstdint>

#define N_VARS_MAX    1000000
#define N_CONSTRS_MAX 500000

__device__ float        g_probs[N_VARS_MAX];
__device__ float        g_ax[N_CONSTRS_MAX];
__device__ double       g_sum;
__device__ unsigned int g_done;

// ---------------------------------------------------------------------------
// Kernel 1: probs = sigmoid(pred) (float4); zero ax (float4); zero scalars
// ---------------------------------------------------------------------------
__global__ void init_kernel(const float* __restrict__ pred, int n_vars, int n_constrs)
{
    int i = blockIdx.x * blockDim.x + threadIdx.x;

    int nv4 = n_vars >> 2;
    if (i < nv4) {
        float4 x = reinterpret_cast<const float4*>(pred)[i];
        float4 p;
        p.x = 1.0f / (1.0f + __expf(-x.x));
        p.y = 1.0f / (1.0f + __expf(-x.y));
        p.z = 1.0f / (1.0f + __expf(-x.z));
        p.w = 1.0f / (1.0f + __expf(-x.w));
        reinterpret_cast<float4*>(g_probs)[i] = p;
    }
    int nc4 = n_constrs >> 2;
    if (i < nc4) {
        reinterpret_cast<float4*>(g_ax)[i] = make_float4(0.f, 0.f, 0.f, 0.f);
    }
    if (i == 0) {
        // scalar tails (n_vars / n_constrs not divisible by 4)
        for (int j = nv4 << 2; j < n_vars; j++)
            g_probs[j] = 1.0f / (1.0f + __expf(-pred[j]));
        for (int j = nc4 << 2; j < n_constrs; j++)
            g_ax[j] = 0.0f;
        g_sum  = 0.0;
        g_done = 0u;
    }
}

// ---------------------------------------------------------------------------
// Kernel 2: scatter — red.global ax[cidx] += coeff * probs[vidx]
// One int4/float4 group (4 nnz) per thread, exact grid, no loop.
// ---------------------------------------------------------------------------
__device__ __forceinline__ void red_add_f32(float* addr, float val)
{
    asm volatile("red.global.add.f32 [%0], %1;" :: "l"(addr), "f"(val) : "memory");
}

__global__ void scatter_kernel(const int*   __restrict__ constr_idx,
                               const int*   __restrict__ var_idx,
                               const float* __restrict__ coeff,
                               int nnz)
{
    int nvec = nnz >> 2;
    int i = blockIdx.x * blockDim.x + threadIdx.x;
    if (i < nvec) {
        int4   ci = reinterpret_cast<const int4*>(constr_idx)[i];
        int4   vi = reinterpret_cast<const int4*>(var_idx)[i];
        float4 co = reinterpret_cast<const float4*>(coeff)[i];

        // 4 independent gathers first (MLP=4) before the REDs
        float p0 = __ldg(&g_probs[vi.x]);
        float p1 = __ldg(&g_probs[vi.y]);
        float p2 = __ldg(&g_probs[vi.z]);
        float p3 = __ldg(&g_probs[vi.w]);

        red_add_f32(&g_ax[ci.x], co.x * p0);
        red_add_f32(&g_ax[ci.y], co.y * p1);
        red_add_f32(&g_ax[ci.z], co.z * p2);
        red_add_f32(&g_ax[ci.w], co.w * p3);
    }
    // tail (nnz % 4): handled by one thread, at most 3 elements
    if (i == 0) {
        for (int j = nvec << 2; j < nnz; j++)
            red_add_f32(&g_ax[constr_idx[j]], coeff[j] * __ldg(&g_probs[var_idx[j]]));
    }
}

// ---------------------------------------------------------------------------
// Kernel 3: violations + two-level reduce; last block writes the mean.
// ---------------------------------------------------------------------------
__global__ void reduce_kernel(const float* __restrict__ rhs,
                              const int*   __restrict__ sense,
                              int n_constrs,
                              float* __restrict__ out,
                              int n_blocks)
{
    float local = 0.0f;
    int stride = gridDim.x * blockDim.x;
    int nc4 = n_constrs >> 2;
    for (int i = blockIdx.x * blockDim.x + threadIdx.x; i < nc4; i += stride) {
        float4 ax = reinterpret_cast<const float4*>(g_ax)[i];
        float4 r  = reinterpret_cast<const float4*>(rhs)[i];
        int4   s  = reinterpret_cast<const int4*>(sense)[i];

        float d0 = ax.x - r.x, d1 = ax.y - r.y, d2 = ax.z - r.z, d3 = ax.w - r.w;
        float v0 = (s.x == 1) ? fmaxf(d0, 0.f) : (s.x == 2) ? fmaxf(-d0, 0.f) : (s.x == 3) ? fabsf(d0) : 0.f;
        float v1 = (s.y == 1) ? fmaxf(d1, 0.f) : (s.y == 2) ? fmaxf(-d1, 0.f) : (s.y == 3) ? fabsf(d1) : 0.f;
        float v2 = (s.z == 1) ? fmaxf(d2, 0.f) : (s.z == 2) ? fmaxf(-d2, 0.f) : (s.z == 3) ? fabsf(d2) : 0.f;
        float v3 = (s.w == 1) ? fmaxf(d3, 0.f) : (s.w == 2) ? fmaxf(-d3, 0.f) : (s.w == 3) ? fabsf(d3) : 0.f;
        local += (v0 + v1) + (v2 + v3);
    }
    // scalar tail
    if (blockIdx.x == 0 && threadIdx.x == 0) {
        for (int j = nc4 << 2; j < n_constrs; j++) {
            float d = g_ax[j] - rhs[j];
            int   s = sense[j];
            local += (s == 1) ? fmaxf(d, 0.f) : (s == 2) ? fmaxf(-d, 0.f) : (s == 3) ? fabsf(d) : 0.f;
        }
    }

    // warp reduce
    #pragma unroll
    for (int off = 16; off > 0; off >>= 1)
        local += __shfl_xor_sync(0xFFFFFFFFu, local, off);

    __shared__ float warp_sums[32];
    int lane = threadIdx.x & 31;
    int wid  = threadIdx.x >> 5;
    if (lane == 0) warp_sums[wid] = local;
    __syncthreads();
    int nwarps = blockDim.x >> 5;

    __shared__ bool is_last;
    if (wid == 0) {
        float b = (lane < nwarps) ? warp_sums[lane] : 0.0f;
        #pragma unroll
        for (int off = 16; off > 0; off >>= 1)
            b += __shfl_xor_sync(0xFFFFFFFFu, b, off);
        if (lane == 0) {
            atomicAdd(&g_sum, (double)b);
            __threadfence();
            unsigned int ticket = atomicInc(&g_done, (unsigned int)(n_blocks - 1));
            is_last = (ticket == (unsigned int)(n_blocks - 1));
        }
    }
    __syncthreads();
    if (is_last && threadIdx.x == 0) {
        out[0] = (float)(g_sum / (double)n_constrs);
    }
}

// ---------------------------------------------------------------------------
// Launch
// ---------------------------------------------------------------------------
extern "C" void kernel_launch(void* const* d_in, const int* in_sizes, int n_in,
                              void* d_out, int out_size)
{
    const float* pred       = (const float*)d_in[0];
    const int*   constr_idx = (const int*)  d_in[1];
    const int*   var_idx    = (const int*)  d_in[2];
    const float* coeff      = (const float*)d_in[3];
    const float* rhs        = (const float*)d_in[4];
    const int*   sense      = (const int*)  d_in[5];

    int n_vars    = in_sizes[0];
    int nnz       = in_sizes[1];
    int n_constrs = in_sizes[4];

    // 1) init (vectorized x4)
    {
        int nv4 = n_vars >> 2, nc4 = n_constrs >> 2;
        int n = (nv4 > nc4) ? nv4 : nc4;
        int threads = 256;
        int blocks  = (n + threads - 1) / threads;
        init_kernel<<<blocks, threads>>>(pred, n_vars, n_constrs);
    }

    // 2) scatter — exact one-shot grid, 4 nnz per thread
    {
        int threads = 256;
        int nvec    = nnz >> 2;
        int blocks  = (nvec + threads - 1) / threads;
        if (blocks < 1) blocks = 1;
        scatter_kernel<<<blocks, threads>>>(constr_idx, var_idx, coeff, nnz);
    }

    // 3) reduce + finalize fused
    {
        int threads = 256;
        int work    = n_constrs >> 2;
        int blocks  = (work + threads * 4 - 1) / (threads * 4);
        if (blocks < 1) blocks = 1;
        reduce_kernel<<<blocks, threads>>>(rhs, sense, n_constrs, (float*)d_out, blocks);
    }
}